// round 10
// baseline (speedup 1.0000x reference)
#include <cuda_runtime.h>
#include <math_constants.h>

#define NFLOWS 8
#define SUBSTR 68            // padded row stride (floats) -> 16B-aligned rows

// ---------------------------------------------------------------------------
// Device-global precomputed tables (no allocations anywhere — harness rule)
// ---------------------------------------------------------------------------
__device__ __align__(16) float  g_hdr[NFLOWS][80];          // [0:64] sorted thr, [64:73] wc, [73:76] c
__device__ __align__(16) float  g_sub[NFLOWS][65 * SUBSTR]; // [s*68+j] sorted sub-breakpoints (+INF pads)
__device__ float4 g_coef[NFLOWS][4225][2];                  // [s*65+j]: {alpha0..3},{beta0..3}
__device__ float  g_L[9], g_bm[3], g_totc;

// ---------------------------------------------------------------------------
// Fused prep: grid (65, 8) x 256 threads. Every block redundantly recomputes
// the per-flow rank sort (cheap). Coef build split 4-ways across threads
// (one (sub-segment j, output r) pair per thread) — was the serial hot loop.
// ALL FP32 (B300 vector fp64 ~2 lane-ops/cyc/SM — R6 regression).
// ---------------------------------------------------------------------------
__global__ __launch_bounds__(256)
void k_prep(const float* __restrict__ L_tril, const float* __restrict__ bm,
            const float* __restrict__ ls, const float* __restrict__ sh,
            const float* __restrict__ P,  const float* __restrict__ ss,
            const float* __restrict__ lm, const float* __restrict__ um,
            const float* __restrict__ lls,
            const float* __restrict__ W1, const float* __restrict__ b1,
            const float* __restrict__ W2, const float* __restrict__ b2,
            const float* __restrict__ W3, const float* __restrict__ b3) {
    __shared__ float  sW2[4096];
    __shared__ float  sa[64], sbv[64], sthr[64], sx[64];
    __shared__ int    srank[64], ssub[64];
    __shared__ float  sP[64], sQ[64];
    __shared__ unsigned char sin_[64], sact0[64];
    __shared__ float  sw3[4][64];
    __shared__ float  sb3v[4];

    const int s = blockIdx.x;   // 0..64
    const int f = blockIdx.y;
    const int t = threadIdx.x;

    for (int i = t; i < 4096; i += 256) sW2[i] = W2[f * 4096 + i];
    if (t < 64) {
        float a = W1[f * 64 + t], b = b1[f * 64 + t];
        sa[t] = a; sbv[t] = b;
        sx[t] = (a != 0.f) ? (-b / a) : CUDART_INF_F;   // raw thresholds (temp in sx)
        sw3[0][t] = W3[f * 256 + t];
        sw3[1][t] = W3[f * 256 + 64 + t];
        sw3[2][t] = W3[f * 256 + 128 + t];
        sw3[3][t] = W3[f * 256 + 192 + t];
    }
    if (t >= 64 && t < 68) sb3v[t - 64] = b3[f * 4 + (t - 64)];
    __syncthreads();

    // per-block redundant rank sort of the 64 layer-1 breakpoints
    if (t < 64) {
        float tk = sx[t];
        int r = 0;
        for (int j = 0; j < 64; ++j) {
            float tj = sx[j];
            r += (tj < tk) || (tj == tk && j < t);
        }
        srank[t] = r;
        sthr[r] = tk;
    }
    __syncthreads();

    // block s==0 of each flow publishes the header
    if (s == 0) {
        if (t < 64) g_hdr[f][t] = sthr[t];
        if (t == 64) {
            float el[3], shv[3];
            for (int d = 0; d < 3; d++) { el[d] = expf(ls[f * 3 + d]); shv[d] = sh[f * 3 + d]; }
            float l[3][3], U[3][3];
            for (int aa = 0; aa < 3; aa++)
                for (int bb = 0; bb < 3; bb++) {
                    l[aa][bb] = (bb < aa ? lm[f * 9 + aa * 3 + bb] : (aa == bb ? 1.f : 0.f));
                    U[aa][bb] = (bb > aa ? um[f * 9 + aa * 3 + bb] : 0.f);
                }
            for (int d = 0; d < 3; d++) U[d][d] = ss[f * 3 + d] * expf(lls[f * 3 + d]);
            float A[3][3], Wm[3][3];
            for (int aa = 0; aa < 3; aa++)
                for (int bb = 0; bb < 3; bb++) {
                    float s2 = 0.f;
                    for (int q = 0; q < 3; q++) s2 += l[aa][q] * U[q][bb];
                    A[aa][bb] = s2;
                }
            for (int aa = 0; aa < 3; aa++)
                for (int bb = 0; bb < 3; bb++) {
                    float s2 = 0.f;
                    for (int q = 0; q < 3; q++) s2 += P[f * 9 + aa * 3 + q] * A[q][bb];
                    Wm[aa][bb] = s2;
                }
            for (int aa = 0; aa < 3; aa++) {
                float cs = 0.f;
                for (int bb = 0; bb < 3; bb++) {
                    float wcv = Wm[aa][bb] * el[bb];
                    g_hdr[f][64 + aa * 3 + bb] = wcv;
                    cs += wcv * shv[bb];
                }
                g_hdr[f][73 + aa] = cs;
            }
        }
        if (f == 0 && t == 65) {
            float Lt[3][3], cov[3][3];
            for (int aa = 0; aa < 3; aa++)
                for (int bb = 0; bb < 3; bb++)
                    Lt[aa][bb] = (bb <= aa ? L_tril[aa * 3 + bb] : 0.f) + (aa == bb ? 1e-6f : 0.f);
            for (int aa = 0; aa < 3; aa++)
                for (int bb = 0; bb < 3; bb++) {
                    float s2 = 0.f;
                    for (int q = 0; q < 3; q++) s2 += Lt[aa][q] * Lt[bb][q];
                    cov[aa][bb] = s2;
                }
            float L00 = sqrtf(cov[0][0]);
            float L10 = cov[1][0] / L00, L20 = cov[2][0] / L00;
            float L11 = sqrtf(cov[1][1] - L10 * L10);
            float L21 = (cov[2][1] - L20 * L10) / L11;
            float L22 = sqrtf(cov[2][2] - L20 * L20 - L21 * L21);
            float Lm[9] = {L00, 0.f, 0.f, L10, L11, 0.f, L20, L21, L22};
            for (int q = 0; q < 9; q++) g_L[q] = Lm[q];
            for (int q = 0; q < 3; q++) g_bm[q] = bm[q];
        }
        if (f == 0 && t == 66) {
            float tot = 0.f;
            for (int q = 0; q < NFLOWS * 3; q++) tot += ls[q] + lls[q];
            g_totc = tot;
        }
    }

    const float lo = (s == 0)  ? -CUDART_INF_F : sthr[s - 1];
    const float hi = (s == 64) ?  CUDART_INF_F : sthr[s];

    if (t < 64) {
        const int u = t;
        float Pd = 0.f, Qd = b2[f * 64 + u];
        for (int j = 0; j < 64; ++j) {
            float aj = sa[j];
            bool act = (aj > 0.f) ? (srank[j] < s)
                     : (aj < 0.f) ? (srank[j] >= s)
                                  : (sbv[j] > 0.f);
            if (act) {
                float w = sW2[u * 64 + j];
                Pd = fmaf(w, aj, Pd);
                Qd = fmaf(w, sbv[j], Qd);
            }
        }
        sP[u] = Pd; sQ[u] = Qd;
        float xu = (Pd != 0.f) ? (-Qd / Pd) : CUDART_INF_F;
        bool inside = (Pd != 0.f) && (xu > lo) && (xu < hi);
        sx[u]  = inside ? xu : CUDART_INF_F;
        sin_[u] = inside ? 1 : 0;
        bool a0;                                // active just above lo?
        if (Pd > 0.f)      a0 = (xu <= lo);
        else if (Pd < 0.f) a0 = (xu > lo);
        else               a0 = (Qd > 0.f);
        sact0[u] = a0 ? 1 : 0;
    }
    __syncthreads();
    if (t < 64) {
        float key = sx[t];
        int r = 0;
        for (int j = 0; j < 64; ++j) {
            float xj = sx[j];
            r += (xj < key) || (xj == key && j < t);
        }
        ssub[t] = r;
        g_sub[f][s * SUBSTR + r] = key;           // sorted (INF entries at top)
    }
    if (t >= 64 && t < 68)                        // pads 64..67 = +INF
        g_sub[f][s * SUBSTR + t] = CUDART_INF_F;
    __syncthreads();

    // coef build: thread t -> (j = t>>2, r = t&3); j=64 handled by t<4 after
    {
        int j = t >> 2, r = t & 3;
        for (int pass = 0; pass < 2; ++pass) {
            if (pass == 1) { if (t >= 4) break; j = 64; r = t; }
            float al = 0.f, be = sb3v[r];
            const float* w3r = sw3[r];
            for (int u = 0; u < 64; ++u) {
                bool act = (sact0[u] != 0) != ((sin_[u] != 0) && (ssub[u] < j));
                if (act) {
                    float w = w3r[u];
                    al = fmaf(w, sP[u], al);
                    be = fmaf(w, sQ[u], be);
                }
            }
            float* dst = (float*)&g_coef[f][s * 65 + j][0];
            dst[r] = al; dst[4 + r] = be;
        }
    }
}

// ---------------------------------------------------------------------------
// Main kernel: 256 thr/CTA, 4 samples/thread. NO shared memory, NO barriers.
// All tables via __ldg (L1-resident: hdr 320B + sub 17.7KB + coef 135KB/flow).
// Coarse: 8 uniform pivot loads -> ALU octant -> one aligned 32B gather.
// Fine: float4 linear scan (avg ~1 load — sub tables are mostly +INF).
// ---------------------------------------------------------------------------
__global__ __launch_bounds__(256)
void glow_main(const float* __restrict__ eps, float* __restrict__ out, int N) {
    const int tid = threadIdx.x;
    int   idx[4];
    bool  vld[4];
    float z0[4], z1[4], z2[4], ldv[4];

    const float L0 = g_L[0], L3 = g_L[3], L4 = g_L[4],
                L6 = g_L[6], L7 = g_L[7], L8 = g_L[8];
    const float m0 = g_bm[0], m1 = g_bm[1], m2 = g_bm[2];

    #pragma unroll
    for (int q = 0; q < 4; ++q) {
        int gi = blockIdx.x * 1024 + q * 256 + tid;
        vld[q] = gi < N;
        int i = vld[q] ? gi : (N - 1);
        idx[q] = i;
        float e0 = eps[3 * i], e1 = eps[3 * i + 1], e2 = eps[3 * i + 2];
        z0[q] = m0 + L0 * e0;
        z1[q] = m1 + L3 * e0 + L4 * e1;
        z2[q] = m2 + L6 * e0 + L7 * e1 + L8 * e2;
        ldv[q] = 0.f;
    }

    for (int f = 0; f < NFLOWS; ++f) {
        const float* hdr = g_hdr[f];

        // conv constants (uniform-address broadcast loads)
        float4 h0 = __ldg((const float4*)(hdr + 64));
        float4 h1 = __ldg((const float4*)(hdr + 68));
        float4 h2 = __ldg((const float4*)(hdr + 72));
        const float w0 = h0.x, w1 = h0.y, w2 = h0.z, w3v = h0.w;
        const float w4 = h1.x, w5 = h1.y, w6 = h1.z, w7 = h1.w;
        const float w8 = h2.x, c0 = h2.y, c1 = h2.z, c2 = h2.w;

        #pragma unroll
        for (int q = 0; q < 4; ++q) {
            float n0 = c0 + w0 * z0[q] + w1 * z1[q] + w2 * z2[q];
            float n1 = c1 + w3v * z0[q] + w4 * z1[q] + w5 * z2[q];
            float n2 = c2 + w6 * z0[q] + w7 * z1[q] + w8 * z2[q];
            z0[q] = n0; z1[q] = n1; z2[q] = n2;
        }

        // pivots thr[7], thr[15], ..., thr[63] (uniform broadcast -> registers)
        float pv[8];
        #pragma unroll
        for (int k = 0; k < 8; ++k) pv[k] = __ldg(hdr + 8 * k + 7);

        // coarse rank s in [0,64]: octant by ALU, then one aligned 8-float gather
        int sS[4];
        float4 t0[4], t1[4];
        #pragma unroll
        for (int q = 0; q < 4; ++q) {
            float x = z0[q];
            int o = (pv[0] < x) + (pv[1] < x) + (pv[2] < x) + (pv[3] < x)
                  + (pv[4] < x) + (pv[5] < x) + (pv[6] < x) + (pv[7] < x);
            int ob = (o > 7 ? 7 : o) * 8;
            sS[q] = ob;
            t0[q] = __ldg((const float4*)(hdr + ob));
            t1[q] = __ldg((const float4*)(hdr + ob + 4));
        }
        #pragma unroll
        for (int q = 0; q < 4; ++q) {
            float x = z0[q];
            sS[q] += (t0[q].x < x) + (t0[q].y < x) + (t0[q].z < x) + (t0[q].w < x)
                   + (t1[q].x < x) + (t1[q].y < x) + (t1[q].z < x) + (t1[q].w < x);
        }

        // fine rank j in [0,64]: float4 linear scan (INF-padded, avg 1 load)
        int jS[4];
        float4 v[4];
        #pragma unroll
        for (int q = 0; q < 4; ++q)
            v[q] = __ldg((const float4*)(g_sub[f] + sS[q] * SUBSTR));
        #pragma unroll
        for (int q = 0; q < 4; ++q) {
            float x = z0[q];
            int c = (v[q].x < x) + (v[q].y < x) + (v[q].z < x) + (v[q].w < x);
            int j = c;
            while (c == 4) {
                float4 w = __ldg((const float4*)(g_sub[f] + sS[q] * SUBSTR) + (j >> 2));
                c = (w.x < x) + (w.y < x) + (w.z < x) + (w.w < x);
                j += c;
            }
            jS[q] = j;
        }

        // exact affine MLP output + coupling
        float4 al[4], be[4];
        #pragma unroll
        for (int q = 0; q < 4; ++q) {
            const float4* cp = &g_coef[f][sS[q] * 65 + jS[q]][0];
            al[q] = __ldg(cp); be[q] = __ldg(cp + 1);
        }
        #pragma unroll
        for (int q = 0; q < 4; ++q) {
            float x = z0[q];
            float o0 = fmaf(al[q].x, x, be[q].x), o1 = fmaf(al[q].y, x, be[q].y);
            float o2 = fmaf(al[q].z, x, be[q].z), o3 = fmaf(al[q].w, x, be[q].w);
            z1[q] = fmaf(z1[q], __expf(o2), o0);
            z2[q] = fmaf(z2[q], __expf(o3), o1);
            ldv[q] += o2 + o3;
        }
    }

    const float totc = g_totc;
    #pragma unroll
    for (int q = 0; q < 4; ++q) {
        if (vld[q]) {
            int i = idx[q];
            out[3 * i]     = z0[q];
            out[3 * i + 1] = __expf(z1[q]);
            out[3 * i + 2] = __expf(z2[q]);
            out[3 * N + i] = ldv[q] + totc + z1[q] + z2[q];
        }
    }
}

// ---------------------------------------------------------------------------
// Launch. Inputs (metadata order): eps, L_tril, base_mean, an_log_scale,
// an_shift, perm_p, sign_s, lu_l, lu_u, lu_log_s, W1, b1, W2, b2, W3, b3
// Output: [z_t (N,3) row-major][log_det (N)] float32 (layout verified R4..R9)
// ---------------------------------------------------------------------------
extern "C" void kernel_launch(void* const* d_in, const int* in_sizes, int n_in,
                              void* d_out, int out_size) {
    const float* eps    = (const float*)d_in[0];
    const float* L_tril = (const float*)d_in[1];
    const float* bm     = (const float*)d_in[2];
    const float* an_ls  = (const float*)d_in[3];
    const float* an_sh  = (const float*)d_in[4];
    const float* perm   = (const float*)d_in[5];
    const float* ss     = (const float*)d_in[6];
    const float* lu_l   = (const float*)d_in[7];
    const float* lu_u   = (const float*)d_in[8];
    const float* lu_ls  = (const float*)d_in[9];
    const float* W1     = (const float*)d_in[10];
    const float* b1     = (const float*)d_in[11];
    const float* W2     = (const float*)d_in[12];
    const float* b2     = (const float*)d_in[13];
    const float* W3     = (const float*)d_in[14];
    const float* b3     = (const float*)d_in[15];
    float* out = (float*)d_out;

    int N = in_sizes[0] / 3;

    k_prep<<<dim3(65, NFLOWS), 256>>>(L_tril, bm, an_ls, an_sh, perm, ss,
                                      lu_l, lu_u, lu_ls, W1, b1, W2, b2, W3, b3);
    glow_main<<<(N + 1023) / 1024, 256>>>(eps, out, N);
}